// round 1
// baseline (speedup 1.0000x reference)
#include <cuda_runtime.h>
#include <mma.h>

using namespace nvcuda;

// ---------------- problem constants ----------------
#define B_DIM   512
#define C_DIM   1024
#define N_TOK   49
#define HEADS   8
#define D_DIM   128
#define KDIM    1024
#define M_TOTAL (B_DIM * N_TOK)      // 25088
#define XSTRIDE (C_DIM * N_TOK)      // 50176 floats per batch in x
#define QKV_SCALE 0.08838834764831845f  // 128^-0.5

// ---------------- scratch (no allocation allowed) ----------------
// q,k,v in (B,H,N,D); attn_out in (B,N,C)
__device__ float g_q[B_DIM * HEADS * N_TOK * D_DIM];
__device__ float g_k[B_DIM * HEADS * N_TOK * D_DIM];
__device__ float g_v[B_DIM * HEADS * N_TOK * D_DIM];
__device__ float g_ao[B_DIM * N_TOK * C_DIM];

// =====================================================================
// Kernel 1: fused QKV projection GEMM (TF32 wmma)
//   A[m,k] = x[b, k, n]   (m = b*49+n)  -> stored col-major in smem
//   Bmat[k,j] = Wrow_j[k] with Wrow_j = Wq[j] (j<1024) else Wkv[j-1024]
//   Epilogue: +bias, (*scale for q), scatter to (B,H,N,D) buffers
// Tiles: BM=64, BN=128, BK=16. 256 threads, 8 warps (2m x 4n), warp 32x32.
// =====================================================================
__global__ __launch_bounds__(256) void qkv_gemm_kernel(
    const float* __restrict__ x,
    const float* __restrict__ Wq,  const float* __restrict__ bq,
    const float* __restrict__ Wkv, const float* __restrict__ bkv)
{
    __shared__ __align__(16) float sbuf[64 * 132];      // 33792 B, reused for C staging
    float* As = sbuf;              // [16][68]  col-major: As[k*68 + m]
    float* Bs = sbuf + 16 * 68;    // [16][132] row-major: Bs[k*132 + j]

    const int tid = threadIdx.x;
    const int m0  = blockIdx.y * 64;
    const int J0  = blockIdx.x * 128;

    // ---- A-load thread mapping (coalesced along m == n) ----
    const int mloc = tid & 63;
    const int kA   = tid >> 6;                 // 0..3
    int rowA = m0 + mloc;
    int bA = rowA / 49;
    int nA = rowA - bA * 49;
    const float* xrow = x + (size_t)bA * XSTRIDE + nA;

    // ---- B-load thread mapping (coalesced along k) ----
    const int kB = tid & 15;
    const int jB = tid >> 4;                   // 0..15
    const float* wptr[8];
    int jidx[8];
#pragma unroll
    for (int i = 0; i < 8; i++) {
        int j = jB + 16 * i;
        int J = J0 + j;
        jidx[i] = j;
        wptr[i] = (J < 1024) ? (Wq + (size_t)J * KDIM)
                             : (Wkv + (size_t)(J - 1024) * KDIM);
    }

    const int wid = tid >> 5;
    const int wm  = wid >> 2;     // 0..1
    const int wn  = wid & 3;      // 0..3

    wmma::fragment<wmma::accumulator, 16, 16, 8, float> cf[2][2];
#pragma unroll
    for (int i = 0; i < 2; i++)
#pragma unroll
        for (int j = 0; j < 2; j++) wmma::fill_fragment(cf[i][j], 0.0f);

    for (int k0 = 0; k0 < KDIM; k0 += 16) {
#pragma unroll
        for (int i = 0; i < 4; i++) {
            int kk = kA + 4 * i;
            As[kk * 68 + mloc] = xrow[(size_t)(k0 + kk) * 49];
        }
#pragma unroll
        for (int i = 0; i < 8; i++)
            Bs[kB * 132 + jidx[i]] = wptr[i][k0 + kB];
        __syncthreads();

#pragma unroll
        for (int ks = 0; ks < 2; ks++) {
            wmma::fragment<wmma::matrix_a, 16, 16, 8, wmma::precision::tf32, wmma::col_major> af[2];
            wmma::fragment<wmma::matrix_b, 16, 16, 8, wmma::precision::tf32, wmma::row_major> bf[2];
#pragma unroll
            for (int i = 0; i < 2; i++) {
                wmma::load_matrix_sync(af[i], As + (ks * 8) * 68 + wm * 32 + 16 * i, 68);
#pragma unroll
                for (int t = 0; t < af[i].num_elements; t++)
                    af[i].x[t] = wmma::__float_to_tf32(af[i].x[t]);
            }
#pragma unroll
            for (int j = 0; j < 2; j++) {
                wmma::load_matrix_sync(bf[j], Bs + (ks * 8) * 132 + wn * 32 + 16 * j, 132);
#pragma unroll
                for (int t = 0; t < bf[j].num_elements; t++)
                    bf[j].x[t] = wmma::__float_to_tf32(bf[j].x[t]);
            }
#pragma unroll
            for (int i = 0; i < 2; i++)
#pragma unroll
                for (int j = 0; j < 2; j++)
                    wmma::mma_sync(cf[i][j], af[i], bf[j], cf[i][j]);
        }
        __syncthreads();
    }

    // ---- epilogue: stage to smem, scatter with bias/scale ----
    float* Cs = sbuf;   // [64][132]
#pragma unroll
    for (int i = 0; i < 2; i++)
#pragma unroll
        for (int j = 0; j < 2; j++)
            wmma::store_matrix_sync(Cs + (wm * 32 + 16 * i) * 132 + wn * 32 + 16 * j,
                                    cf[i][j], 132, wmma::mem_row_major);
    __syncthreads();

#pragma unroll 4
    for (int p = 0; p < 32; p++) {
        int idx = p * 256 + tid;
        int j = idx & 127;
        int i = idx >> 7;
        float v = Cs[i * 132 + j];
        int J = J0 + j;
        int row = m0 + i;
        int b = row / 49;
        int n = row - b * 49;
        if (J < 1024) {
            int c = J;
            int h = c >> 7, d = c & 127;
            g_q[(((size_t)(b * 8 + h)) * 49 + n) * 128 + d] = (v + bq[c]) * QKV_SCALE;
        } else if (J < 2048) {
            int c = J - 1024;
            int h = c >> 7, d = c & 127;
            g_k[(((size_t)(b * 8 + h)) * 49 + n) * 128 + d] = v + bkv[c];
        } else {
            int c = J - 2048;
            int h = c >> 7, d = c & 127;
            g_v[(((size_t)(b * 8 + h)) * 49 + n) * 128 + d] = v + bkv[c + 1024];
        }
    }
}

// =====================================================================
// Kernel 2: attention per (b,h). 256 threads, dynamic smem ~86 KB.
//   scores (fp32, conflict-free ld=129 K tile) + rpb, softmax & relu^2
//   mix, PV with float4. Output to g_ao in (B,N,C).
// =====================================================================
#define ATT_SMEM_FLOATS (6272 + 6336 + 6272 + 49 * 52 + 176)
#define ATT_SMEM_BYTES  (ATT_SMEM_FLOATS * 4)

__global__ __launch_bounds__(256) void attn_kernel(
    const float* __restrict__ rpb_table, const float* __restrict__ w_mix)
{
    extern __shared__ __align__(16) float sm[];
    float* q_s   = sm;                   // 49*128
    float* k_s   = sm + 6272;            // 49 rows, ld 129 (6336 alloc)
    float* v_s   = sm + 6272 + 6336;     // 49*128 (16B aligned)
    float* p_s   = v_s + 6272;           // 49*52
    float* rpb_s = p_s + 49 * 52;        // 169

    const int bh   = blockIdx.x;
    const int h    = bh & 7;
    const int b    = bh >> 3;
    const int tid  = threadIdx.x;
    const int lane = tid & 31;
    const int wid  = tid >> 5;

    const float* qg = g_q + (size_t)bh * 6272;
    const float* kg = g_k + (size_t)bh * 6272;
    const float* vg = g_v + (size_t)bh * 6272;

    for (int i = tid; i < 6272; i += 256) {
        q_s[i] = qg[i];
        v_s[i] = vg[i];
        int m = i >> 7, d = i & 127;
        k_s[m * 129 + d] = kg[i];
    }
    if (tid < 169) rpb_s[tid] = rpb_table[tid * 8 + h];

    // branch weights: softmax(w_mix)
    float wa = w_mix[0], wb = w_mix[1];
    float mw = fmaxf(wa, wb);
    float ea = __expf(wa - mw), eb = __expf(wb - mw);
    float w0 = ea / (ea + eb), w1 = eb / (ea + eb);
    __syncthreads();

    const int m_a = lane;                    // always valid (<=31 < 49)
    const int m_b = lane + 32;
    const bool act = (m_b < 49);
    const int m_bc = act ? m_b : 48;
    const int ja0 = m_a / 7,  ja1 = m_a - ja0 * 7;
    const int jb0 = m_bc / 7, jb1 = m_bc - jb0 * 7;

    for (int n = wid; n < 49; n += 8) {
        float s0 = 0.f, s1 = 0.f;
        const float* qrow = q_s + (n << 7);
        const float* k0p  = k_s + m_a * 129;
        const float* k1p  = k_s + m_bc * 129;
#pragma unroll 8
        for (int d = 0; d < 128; d++) {
            float qd = qrow[d];
            s0 = fmaf(qd, k0p[d], s0);
            s1 = fmaf(qd, k1p[d], s1);
        }
        int i0 = n / 7, i1 = n - i0 * 7;
        s0 += rpb_s[(i0 - ja0 + 6) * 13 + (i1 - ja1 + 6)];
        s1 += rpb_s[(i0 - jb0 + 6) * 13 + (i1 - jb1 + 6)];

        float s1v = act ? s1 : -1e30f;
        float mx = fmaxf(s0, s1v);
#pragma unroll
        for (int off = 16; off > 0; off >>= 1)
            mx = fmaxf(mx, __shfl_xor_sync(0xffffffffu, mx, off));
        float e0 = __expf(s0 - mx);
        float e1 = act ? __expf(s1 - mx) : 0.f;
        float sum = e0 + e1;
#pragma unroll
        for (int off = 16; off > 0; off >>= 1)
            sum += __shfl_xor_sync(0xffffffffu, sum, off);
        float inv = __frcp_rn(sum);

        float r0 = fmaxf(s0, 0.f); r0 *= r0;
        float r1 = fmaxf(s1, 0.f); r1 *= r1;
        p_s[n * 52 + m_a] = w0 * e0 * inv + w1 * r0;
        if (act) p_s[n * 52 + m_b] = w0 * e1 * inv + w1 * r1;
    }
    __syncthreads();

    // PV: lane owns 4 consecutive d
    for (int n = wid; n < 49; n += 8) {
        float4 acc = make_float4(0.f, 0.f, 0.f, 0.f);
        const float* pp = p_s + n * 52;
        const float* vb = v_s + (lane << 2);
#pragma unroll 7
        for (int m = 0; m < 49; m++) {
            float p = pp[m];
            float4 vv = *reinterpret_cast<const float4*>(vb + (m << 7));
            acc.x = fmaf(p, vv.x, acc.x);
            acc.y = fmaf(p, vv.y, acc.y);
            acc.z = fmaf(p, vv.z, acc.z);
            acc.w = fmaf(p, vv.w, acc.w);
        }
        *reinterpret_cast<float4*>(g_ao + ((size_t)(b * 49 + n)) * 1024 + h * 128 + (lane << 2)) = acc;
    }
}

// =====================================================================
// Kernel 3: output projection GEMM (TF32 wmma) with transposed store
//   A = g_ao (row-major M x 1024), B[k,j] = Wproj[j,k]
//   out[b, c, n] = acc + bproj[c]
// =====================================================================
__global__ __launch_bounds__(256) void proj_gemm_kernel(
    const float* __restrict__ Wproj, const float* __restrict__ bproj,
    float* __restrict__ out)
{
    __shared__ __align__(16) float sbuf[64 * 132];
    float* As = sbuf;              // [64][20] row-major: As[m*20 + k]
    float* Bs = sbuf + 64 * 20;    // [16][132]

    const int tid = threadIdx.x;
    const int m0  = blockIdx.y * 64;
    const int J0  = blockIdx.x * 128;

    const int kA = tid & 15;
    const int mA = tid >> 4;                  // 0..15
    const float* arow[4];
#pragma unroll
    for (int i = 0; i < 4; i++)
        arow[i] = g_ao + (size_t)(m0 + mA + 16 * i) * KDIM;

    const int kB = tid & 15;
    const int jB = tid >> 4;
    const float* wptr[8];
    int jidx[8];
#pragma unroll
    for (int i = 0; i < 8; i++) {
        int j = jB + 16 * i;
        jidx[i] = j;
        wptr[i] = Wproj + (size_t)(J0 + j) * KDIM;
    }

    const int wid = tid >> 5;
    const int wm  = wid >> 2;
    const int wn  = wid & 3;

    wmma::fragment<wmma::accumulator, 16, 16, 8, float> cf[2][2];
#pragma unroll
    for (int i = 0; i < 2; i++)
#pragma unroll
        for (int j = 0; j < 2; j++) wmma::fill_fragment(cf[i][j], 0.0f);

    for (int k0 = 0; k0 < KDIM; k0 += 16) {
#pragma unroll
        for (int i = 0; i < 4; i++)
            As[(mA + 16 * i) * 20 + kA] = arow[i][k0 + kA];
#pragma unroll
        for (int i = 0; i < 8; i++)
            Bs[kB * 132 + jidx[i]] = wptr[i][k0 + kB];
        __syncthreads();

#pragma unroll
        for (int ks = 0; ks < 2; ks++) {
            wmma::fragment<wmma::matrix_a, 16, 16, 8, wmma::precision::tf32, wmma::row_major> af[2];
            wmma::fragment<wmma::matrix_b, 16, 16, 8, wmma::precision::tf32, wmma::row_major> bf[2];
#pragma unroll
            for (int i = 0; i < 2; i++) {
                wmma::load_matrix_sync(af[i], As + (wm * 32 + 16 * i) * 20 + ks * 8, 20);
#pragma unroll
                for (int t = 0; t < af[i].num_elements; t++)
                    af[i].x[t] = wmma::__float_to_tf32(af[i].x[t]);
            }
#pragma unroll
            for (int j = 0; j < 2; j++) {
                wmma::load_matrix_sync(bf[j], Bs + (ks * 8) * 132 + wn * 32 + 16 * j, 132);
#pragma unroll
                for (int t = 0; t < bf[j].num_elements; t++)
                    bf[j].x[t] = wmma::__float_to_tf32(bf[j].x[t]);
            }
#pragma unroll
            for (int i = 0; i < 2; i++)
#pragma unroll
                for (int j = 0; j < 2; j++)
                    wmma::mma_sync(cf[i][j], af[i], bf[j], cf[i][j]);
        }
        __syncthreads();
    }

    float* Cs = sbuf;   // [64][132]
#pragma unroll
    for (int i = 0; i < 2; i++)
#pragma unroll
        for (int j = 0; j < 2; j++)
            wmma::store_matrix_sync(Cs + (wm * 32 + 16 * i) * 132 + wn * 32 + 16 * j,
                                    cf[i][j], 132, wmma::mem_row_major);
    __syncthreads();

    // transposed store: i (row, == n) fast for coalescing on out[..., c, n]
#pragma unroll 4
    for (int p = 0; p < 32; p++) {
        int idx = p * 256 + tid;
        int i = idx & 63;
        int j = idx >> 6;
        int J = J0 + j;
        float v = Cs[i * 132 + j] + bproj[J];
        int row = m0 + i;
        int bb = row / 49;
        int nn = row - bb * 49;
        out[(size_t)bb * XSTRIDE + (size_t)J * 49 + nn] = v;
    }
}

// =====================================================================
// launcher
// =====================================================================
extern "C" void kernel_launch(void* const* d_in, const int* in_sizes, int n_in,
                              void* d_out, int out_size)
{
    const float* x         = (const float*)d_in[0];
    const float* Wq        = (const float*)d_in[1];
    const float* bq        = (const float*)d_in[2];
    const float* Wkv       = (const float*)d_in[3];
    const float* bkv       = (const float*)d_in[4];
    const float* rpb_table = (const float*)d_in[5];
    const float* w_mix     = (const float*)d_in[6];
    const float* Wproj     = (const float*)d_in[7];
    const float* bproj     = (const float*)d_in[8];
    float* out = (float*)d_out;

    cudaFuncSetAttribute(attn_kernel, cudaFuncAttributeMaxDynamicSharedMemorySize,
                         ATT_SMEM_BYTES);

    dim3 g1(3072 / 128, M_TOTAL / 64);   // (24, 392)
    qkv_gemm_kernel<<<g1, 256>>>(x, Wq, bq, Wkv, bkv);

    attn_kernel<<<B_DIM * HEADS, 256, ATT_SMEM_BYTES>>>(rpb_table, w_mix);

    dim3 g3(1024 / 128, M_TOTAL / 64);   // (8, 392)
    proj_gemm_kernel<<<g3, 256>>>(Wproj, bproj, out);
}

// round 2
// speedup vs baseline: 1.2173x; 1.2173x over previous
#include <cuda_runtime.h>
#include <mma.h>
#include <cstdint>

using namespace nvcuda;

// ---------------- problem constants ----------------
#define B_DIM   512
#define C_DIM   1024
#define N_TOK   49
#define HEADS   8
#define D_DIM   128
#define KDIM    1024
#define M_TOTAL (B_DIM * N_TOK)      // 25088
#define XSTRIDE (C_DIM * N_TOK)      // 50176 floats per batch in x
#define QKV_SCALE 0.08838834764831845f  // 128^-0.5
#define NSTAGE  4

// ---------------- scratch (no allocation allowed) ----------------
__device__ __align__(16) float g_q[B_DIM * HEADS * N_TOK * D_DIM];
__device__ __align__(16) float g_k[B_DIM * HEADS * N_TOK * D_DIM];
__device__ __align__(16) float g_v[B_DIM * HEADS * N_TOK * D_DIM];
__device__ __align__(16) float g_ao[B_DIM * N_TOK * C_DIM];

// ---------------- cp.async helpers ----------------
__device__ __forceinline__ uint32_t sptr(const void* p) {
    return (uint32_t)__cvta_generic_to_shared(p);
}
__device__ __forceinline__ void cp4(uint32_t d, const void* s) {
    asm volatile("cp.async.ca.shared.global [%0], [%1], 4;\n" :: "r"(d), "l"(s));
}
__device__ __forceinline__ void cp16(uint32_t d, const void* s) {
    asm volatile("cp.async.cg.shared.global [%0], [%1], 16;\n" :: "r"(d), "l"(s));
}
#define CP_COMMIT() asm volatile("cp.async.commit_group;\n")
#define CP_WAIT3()  asm volatile("cp.async.wait_group 3;\n")

// =====================================================================
// Kernel 1: fused QKV projection GEMM (TF32 wmma, pipelined)
// BM=128, BN=256, BK=16, 256 threads, 8 warps (2m x 4n), warp 64x64.
// A[m,k] = x[b,k,n] stored col-major As[k][m] (ld 132)
// B[k,j] = W[j][k]  stored [j][k] (ld 20), wmma col_major matrix_b
// =====================================================================
#define QKV_AS_STG 2112              // 16*132
#define QKV_BS_STG 5120              // 256*20
#define QKV_SMEM_FLOATS (NSTAGE * (QKV_AS_STG + QKV_BS_STG))
#define QKV_SMEM_BYTES  (QKV_SMEM_FLOATS * 4)

__global__ __launch_bounds__(256) void qkv_gemm_kernel(
    const float* __restrict__ x,
    const float* __restrict__ Wq,  const float* __restrict__ bq,
    const float* __restrict__ Wkv, const float* __restrict__ bkv)
{
    extern __shared__ __align__(16) float smp[];
    float* As = smp;                         // NSTAGE * 2112
    float* Bs = smp + NSTAGE * QKV_AS_STG;   // NSTAGE * 5120

    const int tid = threadIdx.x;
    const int m0  = blockIdx.y * 128;
    const int J0  = blockIdx.x * 256;

    // A-load mapping: mA coalesced, each thread loads 8 k values (4B cp.async)
    const int mA = tid & 127;
    const int kh = tid >> 7;                 // 0..1
    const int rowA = m0 + mA;
    const int bA = rowA / 49;
    const int nA = rowA - bA * 49;
    const float* xbase = x + (size_t)bA * XSTRIDE + nA;

    // B-load mapping: 16B cp.async of 4 consecutive k, 4 j-rows per thread
    const int kq = (tid & 3) * 4;
    const int jb = tid >> 2;                 // 0..63
    const float* wrow[4];
    int jloc[4];
#pragma unroll
    for (int i = 0; i < 4; i++) {
        int j = jb + 64 * i;
        int J = J0 + j;
        jloc[i] = j;
        wrow[i] = (J < 1024) ? (Wq + (size_t)J * KDIM)
                             : (Wkv + (size_t)(J - 1024) * KDIM);
    }

    const int wid = tid >> 5;
    const int wm  = wid >> 2;                // 0..1
    const int wn  = wid & 3;                 // 0..3

    wmma::fragment<wmma::accumulator, 16, 16, 8, float> acc[4][4];
#pragma unroll
    for (int i = 0; i < 4; i++)
#pragma unroll
        for (int j = 0; j < 4; j++) wmma::fill_fragment(acc[i][j], 0.0f);

    // prologue: prefetch stages 0..2
#pragma unroll
    for (int st = 0; st < NSTAGE - 1; st++) {
        int k0 = st * 16;
        float* a = As + st * QKV_AS_STG;
        float* b = Bs + st * QKV_BS_STG;
#pragma unroll
        for (int i = 0; i < 8; i++) {
            int k = kh * 8 + i;
            cp4(sptr(a + k * 132 + mA), xbase + (size_t)(k0 + k) * 49);
        }
#pragma unroll
        for (int i = 0; i < 4; i++)
            cp16(sptr(b + jloc[i] * 20 + kq), wrow[i] + k0 + kq);
        CP_COMMIT();
    }

    const int NIT = KDIM / 16;               // 64
    for (int it = 0; it < NIT; it++) {
        // prefetch stage it+3
        if (it + NSTAGE - 1 < NIT) {
            int st = (it + NSTAGE - 1) & (NSTAGE - 1);
            int k0 = (it + NSTAGE - 1) * 16;
            float* a = As + st * QKV_AS_STG;
            float* b = Bs + st * QKV_BS_STG;
#pragma unroll
            for (int i = 0; i < 8; i++) {
                int k = kh * 8 + i;
                cp4(sptr(a + k * 132 + mA), xbase + (size_t)(k0 + k) * 49);
            }
#pragma unroll
            for (int i = 0; i < 4; i++)
                cp16(sptr(b + jloc[i] * 20 + kq), wrow[i] + k0 + kq);
        }
        CP_COMMIT();
        CP_WAIT3();
        __syncthreads();

        const float* a = As + (it & (NSTAGE - 1)) * QKV_AS_STG;
        const float* b = Bs + (it & (NSTAGE - 1)) * QKV_BS_STG;
#pragma unroll
        for (int ks = 0; ks < 2; ks++) {
            const int kk = ks * 8;
            wmma::fragment<wmma::matrix_a, 16, 16, 8, wmma::precision::tf32, wmma::col_major> af[4];
            wmma::fragment<wmma::matrix_b, 16, 16, 8, wmma::precision::tf32, wmma::col_major> bf[4];
#pragma unroll
            for (int i = 0; i < 4; i++) {
                wmma::load_matrix_sync(af[i], a + kk * 132 + wm * 64 + 16 * i, 132);
#pragma unroll
                for (int t = 0; t < af[i].num_elements; t++)
                    af[i].x[t] = wmma::__float_to_tf32(af[i].x[t]);
            }
#pragma unroll
            for (int j = 0; j < 4; j++) {
                wmma::load_matrix_sync(bf[j], b + (wn * 64 + 16 * j) * 20 + kk, 20);
#pragma unroll
                for (int t = 0; t < bf[j].num_elements; t++)
                    bf[j].x[t] = wmma::__float_to_tf32(bf[j].x[t]);
            }
#pragma unroll
            for (int i = 0; i < 4; i++)
#pragma unroll
                for (int j = 0; j < 4; j++)
                    wmma::mma_sync(acc[i][j], af[i], bf[j], acc[i][j]);
        }
        __syncthreads();
    }

    // ---- epilogue: two passes of 128x128 through smem ----
    float* Cs = smp;   // 128 x 132
#pragma unroll
    for (int pass = 0; pass < 2; pass++) {
        if ((wn >> 1) == pass) {
            int cb = (wn & 1) * 64;
#pragma unroll
            for (int i = 0; i < 4; i++)
#pragma unroll
                for (int j = 0; j < 4; j++)
                    wmma::store_matrix_sync(Cs + (wm * 64 + 16 * i) * 132 + cb + 16 * j,
                                            acc[i][j], 132, wmma::mem_row_major);
        }
        __syncthreads();

        const int Jbase = J0 + pass * 128;
#pragma unroll 4
        for (int t = 0; t < 64; t++) {
            int idx = t * 256 + tid;
            int j = idx & 127;
            int i = idx >> 7;
            float v = Cs[i * 132 + j];
            int J = Jbase + j;
            int row = m0 + i;
            int b = row / 49;
            int n = row - b * 49;
            if (J < 1024) {
                int c = J;
                int h = c >> 7, d = c & 127;
                g_q[(((size_t)(b * 8 + h)) * 49 + n) * 128 + d] = (v + bq[c]) * QKV_SCALE;
            } else if (J < 2048) {
                int c = J - 1024;
                int h = c >> 7, d = c & 127;
                g_k[(((size_t)(b * 8 + h)) * 49 + n) * 128 + d] = v + bkv[c];
            } else {
                int c = J - 2048;
                int h = c >> 7, d = c & 127;
                g_v[(((size_t)(b * 8 + h)) * 49 + n) * 128 + d] = v + bkv[c + 1024];
            }
        }
        __syncthreads();
    }
}

// =====================================================================
// Kernel 2: attention per (b,h) — unchanged from round 1
// =====================================================================
#define ATT_SMEM_FLOATS (6272 + 6336 + 6272 + 49 * 52 + 176)
#define ATT_SMEM_BYTES  (ATT_SMEM_FLOATS * 4)

__global__ __launch_bounds__(256) void attn_kernel(
    const float* __restrict__ rpb_table, const float* __restrict__ w_mix)
{
    extern __shared__ __align__(16) float sm[];
    float* q_s   = sm;                   // 49*128
    float* k_s   = sm + 6272;            // 49 rows, ld 129
    float* v_s   = sm + 6272 + 6336;     // 49*128
    float* p_s   = v_s + 6272;           // 49*52
    float* rpb_s = p_s + 49 * 52;        // 169

    const int bh   = blockIdx.x;
    const int h    = bh & 7;
    const int b    = bh >> 3;
    const int tid  = threadIdx.x;
    const int lane = tid & 31;
    const int wid  = tid >> 5;

    const float* qg = g_q + (size_t)bh * 6272;
    const float* kg = g_k + (size_t)bh * 6272;
    const float* vg = g_v + (size_t)bh * 6272;

    for (int i = tid; i < 6272; i += 256) {
        q_s[i] = qg[i];
        v_s[i] = vg[i];
        int m = i >> 7, d = i & 127;
        k_s[m * 129 + d] = kg[i];
    }
    if (tid < 169) rpb_s[tid] = rpb_table[tid * 8 + h];

    float wa = w_mix[0], wb = w_mix[1];
    float mw = fmaxf(wa, wb);
    float ea = __expf(wa - mw), eb = __expf(wb - mw);
    float w0 = ea / (ea + eb), w1 = eb / (ea + eb);
    __syncthreads();

    const int m_a = lane;
    const int m_b = lane + 32;
    const bool act = (m_b < 49);
    const int m_bc = act ? m_b : 48;
    const int ja0 = m_a / 7,  ja1 = m_a - ja0 * 7;
    const int jb0 = m_bc / 7, jb1 = m_bc - jb0 * 7;

    for (int n = wid; n < 49; n += 8) {
        float s0 = 0.f, s1 = 0.f;
        const float* qrow = q_s + (n << 7);
        const float* k0p  = k_s + m_a * 129;
        const float* k1p  = k_s + m_bc * 129;
#pragma unroll 8
        for (int d = 0; d < 128; d++) {
            float qd = qrow[d];
            s0 = fmaf(qd, k0p[d], s0);
            s1 = fmaf(qd, k1p[d], s1);
        }
        int i0 = n / 7, i1 = n - i0 * 7;
        s0 += rpb_s[(i0 - ja0 + 6) * 13 + (i1 - ja1 + 6)];
        s1 += rpb_s[(i0 - jb0 + 6) * 13 + (i1 - jb1 + 6)];

        float s1v = act ? s1 : -1e30f;
        float mx = fmaxf(s0, s1v);
#pragma unroll
        for (int off = 16; off > 0; off >>= 1)
            mx = fmaxf(mx, __shfl_xor_sync(0xffffffffu, mx, off));
        float e0 = __expf(s0 - mx);
        float e1 = act ? __expf(s1 - mx) : 0.f;
        float sum = e0 + e1;
#pragma unroll
        for (int off = 16; off > 0; off >>= 1)
            sum += __shfl_xor_sync(0xffffffffu, sum, off);
        float inv = __frcp_rn(sum);

        float r0 = fmaxf(s0, 0.f); r0 *= r0;
        float r1 = fmaxf(s1, 0.f); r1 *= r1;
        p_s[n * 52 + m_a] = w0 * e0 * inv + w1 * r0;
        if (act) p_s[n * 52 + m_b] = w0 * e1 * inv + w1 * r1;
    }
    __syncthreads();

    for (int n = wid; n < 49; n += 8) {
        float4 acc = make_float4(0.f, 0.f, 0.f, 0.f);
        const float* pp = p_s + n * 52;
        const float* vb = v_s + (lane << 2);
#pragma unroll 7
        for (int m = 0; m < 49; m++) {
            float p = pp[m];
            float4 vv = *reinterpret_cast<const float4*>(vb + (m << 7));
            acc.x = fmaf(p, vv.x, acc.x);
            acc.y = fmaf(p, vv.y, acc.y);
            acc.z = fmaf(p, vv.z, acc.z);
            acc.w = fmaf(p, vv.w, acc.w);
        }
        *reinterpret_cast<float4*>(g_ao + ((size_t)(b * 49 + n)) * 1024 + h * 128 + (lane << 2)) = acc;
    }
}

// =====================================================================
// Kernel 3: output projection GEMM (TF32 wmma, pipelined)
// BM=128, BN=256, BK=16. A = g_ao row-major (ld 20 in smem).
// Epilogue: +bias, transposed store out[b, c, n].
// =====================================================================
#define PRJ_AS_STG 2560              // 128*20
#define PRJ_BS_STG 5120              // 256*20
#define PRJ_SMEM_FLOATS (NSTAGE * (PRJ_AS_STG + PRJ_BS_STG))
#define PRJ_SMEM_BYTES  (PRJ_SMEM_FLOATS * 4)

__global__ __launch_bounds__(256) void proj_gemm_kernel(
    const float* __restrict__ Wproj, const float* __restrict__ bproj,
    float* __restrict__ out)
{
    extern __shared__ __align__(16) float smp[];
    float* As = smp;                          // NSTAGE * 2560
    float* Bs = smp + NSTAGE * PRJ_AS_STG;    // NSTAGE * 5120

    const int tid = threadIdx.x;
    const int m0  = blockIdx.y * 128;
    const int J0  = blockIdx.x * 256;

    // A-load: 16B cp.async, 2 m-rows per thread
    const int kqA = (tid & 3) * 4;
    const int mr  = tid >> 2;                 // 0..63
    const float* abase0 = g_ao + (size_t)(m0 + mr) * KDIM + kqA;
    const float* abase1 = g_ao + (size_t)(m0 + mr + 64) * KDIM + kqA;

    // B-load: same as qkv
    const int kq = (tid & 3) * 4;
    const int jb = tid >> 2;
    const float* wrow[4];
    int jloc[4];
#pragma unroll
    for (int i = 0; i < 4; i++) {
        int j = jb + 64 * i;
        jloc[i] = j;
        wrow[i] = Wproj + (size_t)(J0 + j) * KDIM;
    }

    const int wid = tid >> 5;
    const int wm  = wid >> 2;
    const int wn  = wid & 3;

    wmma::fragment<wmma::accumulator, 16, 16, 8, float> acc[4][4];
#pragma unroll
    for (int i = 0; i < 4; i++)
#pragma unroll
        for (int j = 0; j < 4; j++) wmma::fill_fragment(acc[i][j], 0.0f);

#pragma unroll
    for (int st = 0; st < NSTAGE - 1; st++) {
        int k0 = st * 16;
        float* a = As + st * PRJ_AS_STG;
        float* b = Bs + st * PRJ_BS_STG;
        cp16(sptr(a + mr * 20 + kqA), abase0 + k0);
        cp16(sptr(a + (mr + 64) * 20 + kqA), abase1 + k0);
#pragma unroll
        for (int i = 0; i < 4; i++)
            cp16(sptr(b + jloc[i] * 20 + kq), wrow[i] + k0 + kq);
        CP_COMMIT();
    }

    const int NIT = KDIM / 16;
    for (int it = 0; it < NIT; it++) {
        if (it + NSTAGE - 1 < NIT) {
            int st = (it + NSTAGE - 1) & (NSTAGE - 1);
            int k0 = (it + NSTAGE - 1) * 16;
            float* a = As + st * PRJ_AS_STG;
            float* b = Bs + st * PRJ_BS_STG;
            cp16(sptr(a + mr * 20 + kqA), abase0 + k0);
            cp16(sptr(a + (mr + 64) * 20 + kqA), abase1 + k0);
#pragma unroll
            for (int i = 0; i < 4; i++)
                cp16(sptr(b + jloc[i] * 20 + kq), wrow[i] + k0 + kq);
        }
        CP_COMMIT();
        CP_WAIT3();
        __syncthreads();

        const float* a = As + (it & (NSTAGE - 1)) * PRJ_AS_STG;
        const float* b = Bs + (it & (NSTAGE - 1)) * PRJ_BS_STG;
#pragma unroll
        for (int ks = 0; ks < 2; ks++) {
            const int kk = ks * 8;
            wmma::fragment<wmma::matrix_a, 16, 16, 8, wmma::precision::tf32, wmma::row_major> af[4];
            wmma::fragment<wmma::matrix_b, 16, 16, 8, wmma::precision::tf32, wmma::col_major> bf[4];
#pragma unroll
            for (int i = 0; i < 4; i++) {
                wmma::load_matrix_sync(af[i], a + (wm * 64 + 16 * i) * 20 + kk, 20);
#pragma unroll
                for (int t = 0; t < af[i].num_elements; t++)
                    af[i].x[t] = wmma::__float_to_tf32(af[i].x[t]);
            }
#pragma unroll
            for (int j = 0; j < 4; j++) {
                wmma::load_matrix_sync(bf[j], b + (wn * 64 + 16 * j) * 20 + kk, 20);
#pragma unroll
                for (int t = 0; t < bf[j].num_elements; t++)
                    bf[j].x[t] = wmma::__float_to_tf32(bf[j].x[t]);
            }
#pragma unroll
            for (int i = 0; i < 4; i++)
#pragma unroll
                for (int j = 0; j < 4; j++)
                    wmma::mma_sync(acc[i][j], af[i], bf[j], acc[i][j]);
        }
        __syncthreads();
    }

    // ---- epilogue: two passes, transposed store ----
    float* Cs = smp;   // 128 x 132
#pragma unroll
    for (int pass = 0; pass < 2; pass++) {
        if ((wn >> 1) == pass) {
            int cb = (wn & 1) * 64;
#pragma unroll
            for (int i = 0; i < 4; i++)
#pragma unroll
                for (int j = 0; j < 4; j++)
                    wmma::store_matrix_sync(Cs + (wm * 64 + 16 * i) * 132 + cb + 16 * j,
                                            acc[i][j], 132, wmma::mem_row_major);
        }
        __syncthreads();

        const int Jbase = J0 + pass * 128;
#pragma unroll 4
        for (int t = 0; t < 64; t++) {
            int idx = t * 256 + tid;
            int i = idx & 127;          // row (= n dim), fast for coalescing
            int j = idx >> 7;
            int J = Jbase + j;
            float v = Cs[i * 132 + j] + bproj[J];
            int row = m0 + i;
            int bb = row / 49;
            int nn = row - bb * 49;
            out[(size_t)bb * XSTRIDE + (size_t)J * 49 + nn] = v;
        }
        __syncthreads();
    }
}

// =====================================================================
// launcher
// =====================================================================
extern "C" void kernel_launch(void* const* d_in, const int* in_sizes, int n_in,
                              void* d_out, int out_size)
{
    const float* x         = (const float*)d_in[0];
    const float* Wq        = (const float*)d_in[1];
    const float* bq        = (const float*)d_in[2];
    const float* Wkv       = (const float*)d_in[3];
    const float* bkv       = (const float*)d_in[4];
    const float* rpb_table = (const float*)d_in[5];
    const float* w_mix     = (const float*)d_in[6];
    const float* Wproj     = (const float*)d_in[7];
    const float* bproj     = (const float*)d_in[8];
    float* out = (float*)d_out;

    cudaFuncSetAttribute(qkv_gemm_kernel, cudaFuncAttributeMaxDynamicSharedMemorySize,
                         QKV_SMEM_BYTES);
    cudaFuncSetAttribute(attn_kernel, cudaFuncAttributeMaxDynamicSharedMemorySize,
                         ATT_SMEM_BYTES);
    cudaFuncSetAttribute(proj_gemm_kernel, cudaFuncAttributeMaxDynamicSharedMemorySize,
                         PRJ_SMEM_BYTES);

    dim3 g1(3072 / 256, M_TOTAL / 128);   // (12, 196)
    qkv_gemm_kernel<<<g1, 256, QKV_SMEM_BYTES>>>(x, Wq, bq, Wkv, bkv);

    attn_kernel<<<B_DIM * HEADS, 256, ATT_SMEM_BYTES>>>(rpb_table, w_mix);

    dim3 g3(1024 / 256, M_TOTAL / 128);   // (4, 196)
    proj_gemm_kernel<<<g3, 256, PRJ_SMEM_BYTES>>>(Wproj, bproj, out);
}

// round 7
// speedup vs baseline: 1.2441x; 1.0220x over previous
#include <cuda_runtime.h>
#include <mma.h>
#include <cstdint>

using namespace nvcuda;

// ---------------- problem constants ----------------
#define B_DIM   512
#define C_DIM   1024
#define N_TOK   49
#define HEADS   8
#define KDIM    1024
#define M_TOTAL (B_DIM * N_TOK)      // 25088
#define XSTRIDE (C_DIM * N_TOK)      // 50176
#define QKV_SCALE 0.08838834764831845f
#define NSTAGE  3
#define BKT     32                   // k per stage
#define NIT     (KDIM / BKT)         // 32
#define LDA     36                   // smem leading dim (32 + 4 pad)

// ---------------- scratch (tf32-pre-rounded fp32 operands) ----------------
__device__ __align__(16) float g_a [(size_t)M_TOTAL * KDIM];   // x transposed [M,K]
__device__ __align__(16) float g_wc[3072 * KDIM];              // [Wq;Wkv] rows
__device__ __align__(16) float g_wp[1024 * KDIM];              // Wproj rows
__device__ __align__(16) float g_q [(size_t)M_TOTAL * C_DIM];
__device__ __align__(16) float g_k [(size_t)M_TOTAL * C_DIM];
__device__ __align__(16) float g_v [(size_t)M_TOTAL * C_DIM];
__device__ __align__(16) float g_ao[(size_t)M_TOTAL * C_DIM];  // attn out [M,K] (tf32-rounded)

// ---------------- helpers ----------------
__device__ __forceinline__ float to_tf32(float x) {
    uint32_t r;                       // tf32 cvt needs a .b32 destination
    asm("cvt.rna.tf32.f32 %0, %1;" : "=r"(r) : "f"(x));
    return __uint_as_float(r);
}
__device__ __forceinline__ uint32_t sptr(const void* p) {
    return (uint32_t)__cvta_generic_to_shared(p);
}
__device__ __forceinline__ void cp16(uint32_t d, const void* s) {
    asm volatile("cp.async.cg.shared.global [%0], [%1], 16;\n" :: "r"(d), "l"(s));
}
#define CP_COMMIT() asm volatile("cp.async.commit_group;\n")
#define CP_WAIT2()  asm volatile("cp.async.wait_group 2;\n")

// ---------------- smem stage layout (floats) ----------------
// stage s: A (128 x LDA) then B (128 x LDA)
#define AS_FLOATS (128 * LDA)                 // 4608
#define STG_FLOATS (2 * AS_FLOATS)            // 9216
#define GEMM_SMEM_BYTES (NSTAGE * STG_FLOATS * 4)   // 110592

// =====================================================================
// prep: transpose x (B, C, 49) -> g_a[(b*49+n), k], tf32-rounded
// =====================================================================
__global__ __launch_bounds__(256) void xprep_kernel(const float* __restrict__ x)
{
    __shared__ float tile[32][50];
    const int b  = blockIdx.y;
    const int k0 = blockIdx.x * 32;
    const float* xb = x + (size_t)b * XSTRIDE + (size_t)k0 * 49;
    for (int idx = threadIdx.x; idx < 32 * 49; idx += 256) {
        int kk = idx / 49, nn = idx - kk * 49;
        tile[kk][nn] = xb[idx];
    }
    __syncthreads();
    for (int idx = threadIdx.x; idx < 49 * 32; idx += 256) {
        int nn = idx >> 5, kk = idx & 31;
        g_a[(size_t)(b * 49 + nn) * KDIM + k0 + kk] = to_tf32(tile[kk][nn]);
    }
}

// =====================================================================
// prep: round weights to tf32. sel: 0=Wq->wc[0:], 1=Wkv->wc[1024K:], 2=Wproj->wp
// =====================================================================
__global__ __launch_bounds__(256) void wprep_kernel(
    const float* __restrict__ src, int sel, int nelem)
{
    int i = (blockIdx.x * 256 + threadIdx.x) * 4;
    if (i >= nelem) return;
    float* dst;
    if (sel == 0)      dst = g_wc;
    else if (sel == 1) dst = g_wc + 1024 * KDIM;
    else               dst = g_wp;
    float4 v = *reinterpret_cast<const float4*>(src + i);
    v.x = to_tf32(v.x); v.y = to_tf32(v.y);
    v.z = to_tf32(v.z); v.w = to_tf32(v.w);
    *reinterpret_cast<float4*>(dst + i) = v;
}

// =====================================================================
// GEMM mainloop: acc[2][4] (warp 32x64), CTA 128x128, BK=32, 3-stage
// A row-major [m][k] in smem (ld 36); B as [j][k] (ld 36), col_major frag.
// =====================================================================
using FragA = wmma::fragment<wmma::matrix_a, 16, 16, 8, wmma::precision::tf32, wmma::row_major>;
using FragB = wmma::fragment<wmma::matrix_b, 16, 16, 8, wmma::precision::tf32, wmma::col_major>;
using FragC = wmma::fragment<wmma::accumulator, 16, 16, 8, float>;

__device__ __forceinline__ void gemm_mainloop(
    float* smp, const float* __restrict__ A, const float* __restrict__ W,
    int m0, int J0, FragC acc[2][4])
{
    const int tid = threadIdx.x;
    const int wid = tid >> 5;
    const int wm  = wid & 3;          // 0..3 (M)
    const int wn  = wid >> 2;         // 0..1 (N)

    const int r0 = tid >> 3;          // 0..31
    const int kq = (tid & 7) * 4;

#pragma unroll
    for (int i = 0; i < 2; i++)
#pragma unroll
        for (int j = 0; j < 4; j++) wmma::fill_fragment(acc[i][j], 0.0f);

    auto load_stage = [&](int s, int k0) {
        float* As = smp + s * STG_FLOATS;
        float* Bs = As + AS_FLOATS;
#pragma unroll
        for (int i = 0; i < 4; i++) {
            int row = r0 + 32 * i;
            cp16(sptr(As + row * LDA + kq), A + (size_t)(m0 + row) * KDIM + k0 + kq);
            cp16(sptr(Bs + row * LDA + kq), W + (size_t)(J0 + row) * KDIM + k0 + kq);
        }
    };

    load_stage(0, 0);
    CP_COMMIT();
    load_stage(1, BKT);
    CP_COMMIT();

    for (int it = 0; it < NIT; it++) {
        if (it + NSTAGE - 1 < NIT) {
            int st = it + NSTAGE - 1;
            load_stage(st % NSTAGE, st * BKT);
        }
        CP_COMMIT();
        CP_WAIT2();
        __syncthreads();

        const float* As = smp + (it % NSTAGE) * STG_FLOATS;
        const float* Bs = As + AS_FLOATS;
#pragma unroll
        for (int ks = 0; ks < 4; ks++) {
            const int kk = ks * 8;
            FragA af[2];
            FragB bf[4];
#pragma unroll
            for (int i = 0; i < 2; i++)
                wmma::load_matrix_sync(af[i], As + (wm * 32 + 16 * i) * LDA + kk, LDA);
#pragma unroll
            for (int j = 0; j < 4; j++)
                wmma::load_matrix_sync(bf[j], Bs + (wn * 64 + 16 * j) * LDA + kk, LDA);
#pragma unroll
            for (int i = 0; i < 2; i++)
#pragma unroll
                for (int j = 0; j < 4; j++)
                    wmma::mma_sync(acc[i][j], af[i], bf[j], acc[i][j]);
        }
        __syncthreads();
    }
}

// stage accumulators to smem Cs (128 x 132)
__device__ __forceinline__ void stage_acc(float* Cs, FragC acc[2][4])
{
    const int wid = threadIdx.x >> 5;
    const int wm  = wid & 3;
    const int wn  = wid >> 2;
#pragma unroll
    for (int i = 0; i < 2; i++)
#pragma unroll
        for (int j = 0; j < 4; j++)
            wmma::store_matrix_sync(Cs + (wm * 32 + 16 * i) * 132 + wn * 64 + 16 * j,
                                    acc[i][j], 132, wmma::mem_row_major);
}

// =====================================================================
// Kernel: QKV GEMM. grid (24, 196). Scatter epilogue with bias/scale.
// =====================================================================
__global__ __launch_bounds__(256, 2) void qkv_gemm_kernel(
    const float* __restrict__ bq, const float* __restrict__ bkv)
{
    extern __shared__ __align__(16) float smp[];
    const int m0 = blockIdx.y * 128;
    const int J0 = blockIdx.x * 128;
    const int tid = threadIdx.x;

    FragC acc[2][4];
    gemm_mainloop(smp, g_a, g_wc, m0, J0, acc);

    float* Cs = smp;
    __syncthreads();
    stage_acc(Cs, acc);
    __syncthreads();

#pragma unroll 4
    for (int p = 0; p < 64; p++) {
        int idx = p * 256 + tid;
        int j = idx & 127;
        int i = idx >> 7;
        float v = Cs[i * 132 + j];
        int J = J0 + j;
        int row = m0 + i;
        int b = row / 49;
        int n = row - b * 49;
        if (J < 1024) {
            int c = J;
            g_q[(((size_t)(b * 8 + (c >> 7))) * 49 + n) * 128 + (c & 127)] =
                (v + bq[c]) * QKV_SCALE;
        } else if (J < 2048) {
            int c = J - 1024;
            g_k[(((size_t)(b * 8 + (c >> 7))) * 49 + n) * 128 + (c & 127)] = v + bkv[c];
        } else {
            int c = J - 2048;
            g_v[(((size_t)(b * 8 + (c >> 7))) * 49 + n) * 128 + (c & 127)] = v + bkv[c + 1024];
        }
    }
}

// =====================================================================
// Kernel: attention per (b,h). Output tf32-rounded to g_ao (B,N,C).
// =====================================================================
#define ATT_SMEM_FLOATS (6272 + 6336 + 6272 + 49 * 52 + 176)
#define ATT_SMEM_BYTES  (ATT_SMEM_FLOATS * 4)

__global__ __launch_bounds__(256) void attn_kernel(
    const float* __restrict__ rpb_table, const float* __restrict__ w_mix)
{
    extern __shared__ __align__(16) float sm[];
    float* q_s   = sm;
    float* k_s   = sm + 6272;
    float* v_s   = sm + 6272 + 6336;
    float* p_s   = v_s + 6272;
    float* rpb_s = p_s + 49 * 52;

    const int bh   = blockIdx.x;
    const int h    = bh & 7;
    const int b    = bh >> 3;
    const int tid  = threadIdx.x;
    const int lane = tid & 31;
    const int wid  = tid >> 5;

    const float* qg = g_q + (size_t)bh * 6272;
    const float* kg = g_k + (size_t)bh * 6272;
    const float* vg = g_v + (size_t)bh * 6272;

    for (int i = tid; i < 6272; i += 256) {
        q_s[i] = qg[i];
        v_s[i] = vg[i];
        int m = i >> 7, d = i & 127;
        k_s[m * 129 + d] = kg[i];
    }
    if (tid < 169) rpb_s[tid] = rpb_table[tid * 8 + h];

    float wa = w_mix[0], wb = w_mix[1];
    float mw = fmaxf(wa, wb);
    float ea = __expf(wa - mw), eb = __expf(wb - mw);
    float w0 = ea / (ea + eb), w1 = eb / (ea + eb);
    __syncthreads();

    const int m_a = lane;
    const int m_b = lane + 32;
    const bool act = (m_b < 49);
    const int m_bc = act ? m_b : 48;
    const int ja0 = m_a / 7,  ja1 = m_a - ja0 * 7;
    const int jb0 = m_bc / 7, jb1 = m_bc - jb0 * 7;

    for (int n = wid; n < 49; n += 8) {
        float s0 = 0.f, s1 = 0.f;
        const float* qrow = q_s + (n << 7);
        const float* k0p  = k_s + m_a * 129;
        const float* k1p  = k_s + m_bc * 129;
#pragma unroll 8
        for (int d = 0; d < 128; d++) {
            float qd = qrow[d];
            s0 = fmaf(qd, k0p[d], s0);
            s1 = fmaf(qd, k1p[d], s1);
        }
        int i0 = n / 7, i1 = n - i0 * 7;
        s0 += rpb_s[(i0 - ja0 + 6) * 13 + (i1 - ja1 + 6)];
        s1 += rpb_s[(i0 - jb0 + 6) * 13 + (i1 - jb1 + 6)];

        float s1v = act ? s1 : -1e30f;
        float mx = fmaxf(s0, s1v);
#pragma unroll
        for (int off = 16; off > 0; off >>= 1)
            mx = fmaxf(mx, __shfl_xor_sync(0xffffffffu, mx, off));
        float e0 = __expf(s0 - mx);
        float e1 = act ? __expf(s1 - mx) : 0.f;
        float sum = e0 + e1;
#pragma unroll
        for (int off = 16; off > 0; off >>= 1)
            sum += __shfl_xor_sync(0xffffffffu, sum, off);
        float inv = __frcp_rn(sum);

        float r0 = fmaxf(s0, 0.f); r0 *= r0;
        float r1 = fmaxf(s1, 0.f); r1 *= r1;
        p_s[n * 52 + m_a] = w0 * e0 * inv + w1 * r0;
        if (act) p_s[n * 52 + m_b] = w0 * e1 * inv + w1 * r1;
    }
    __syncthreads();

    for (int n = wid; n < 49; n += 8) {
        float4 acc = make_float4(0.f, 0.f, 0.f, 0.f);
        const float* pp = p_s + n * 52;
        const float* vb = v_s + (lane << 2);
#pragma unroll 7
        for (int m = 0; m < 49; m++) {
            float p = pp[m];
            float4 vv = *reinterpret_cast<const float4*>(vb + (m << 7));
            acc.x = fmaf(p, vv.x, acc.x);
            acc.y = fmaf(p, vv.y, acc.y);
            acc.z = fmaf(p, vv.z, acc.z);
            acc.w = fmaf(p, vv.w, acc.w);
        }
        acc.x = to_tf32(acc.x);
        acc.y = to_tf32(acc.y);
        acc.z = to_tf32(acc.z);
        acc.w = to_tf32(acc.w);
        *reinterpret_cast<float4*>(
            g_ao + ((size_t)(b * 49 + n)) * 1024 + h * 128 + (lane << 2)) = acc;
    }
}

// =====================================================================
// Kernel: output projection GEMM. grid (8, 196). Transposed store + bias.
// =====================================================================
__global__ __launch_bounds__(256, 2) void proj_gemm_kernel(
    const float* __restrict__ bproj, float* __restrict__ out)
{
    extern __shared__ __align__(16) float smp[];
    const int m0 = blockIdx.y * 128;
    const int J0 = blockIdx.x * 128;
    const int tid = threadIdx.x;

    FragC acc[2][4];
    gemm_mainloop(smp, g_ao, g_wp, m0, J0, acc);

    float* Cs = smp;
    __syncthreads();
    stage_acc(Cs, acc);
    __syncthreads();

    // transposed store: i (row == n) fast for coalescing on out[b, c, n]
#pragma unroll 4
    for (int p = 0; p < 64; p++) {
        int idx = p * 256 + tid;
        int i = idx & 127;
        int j = idx >> 7;
        int J = J0 + j;
        float v = Cs[i * 132 + j] + bproj[J];
        int row = m0 + i;
        int bb = row / 49;
        int nn = row - bb * 49;
        out[(size_t)bb * XSTRIDE + (size_t)J * 49 + nn] = v;
    }
}

// =====================================================================
// launcher
// =====================================================================
extern "C" void kernel_launch(void* const* d_in, const int* in_sizes, int n_in,
                              void* d_out, int out_size)
{
    const float* x         = (const float*)d_in[0];
    const float* Wq        = (const float*)d_in[1];
    const float* bq        = (const float*)d_in[2];
    const float* Wkv       = (const float*)d_in[3];
    const float* bkv       = (const float*)d_in[4];
    const float* rpb_table = (const float*)d_in[5];
    const float* w_mix     = (const float*)d_in[6];
    const float* Wproj     = (const float*)d_in[7];
    const float* bproj     = (const float*)d_in[8];
    float* out = (float*)d_out;

    cudaFuncSetAttribute(qkv_gemm_kernel,
        cudaFuncAttributeMaxDynamicSharedMemorySize, GEMM_SMEM_BYTES);
    cudaFuncSetAttribute(proj_gemm_kernel,
        cudaFuncAttributeMaxDynamicSharedMemorySize, GEMM_SMEM_BYTES);
    cudaFuncSetAttribute(attn_kernel,
        cudaFuncAttributeMaxDynamicSharedMemorySize, ATT_SMEM_BYTES);

    // preps
    dim3 gx(32, 512);
    xprep_kernel<<<gx, 256>>>(x);
    wprep_kernel<<<(1024 * KDIM) / 1024, 256>>>(Wq, 0, 1024 * KDIM);
    wprep_kernel<<<(2048 * KDIM) / 1024, 256>>>(Wkv, 1, 2048 * KDIM);
    wprep_kernel<<<(1024 * KDIM) / 1024, 256>>>(Wproj, 2, 1024 * KDIM);

    dim3 g1(24, 196);
    qkv_gemm_kernel<<<g1, 256, GEMM_SMEM_BYTES>>>(bq, bkv);

    attn_kernel<<<B_DIM * HEADS, 256, ATT_SMEM_BYTES>>>(rpb_table, w_mix);

    dim3 g3(8, 196);
    proj_gemm_kernel<<<g3, 256, GEMM_SMEM_BYTES>>>(bproj, out);
}

// round 10
// speedup vs baseline: 3.3081x; 2.6590x over previous
#include <cuda_runtime.h>
#include <cuda_fp16.h>
#include <mma.h>
#include <cstdint>

using namespace nvcuda;

// ---------------- problem constants ----------------
#define B_DIM   512
#define C_DIM   1024
#define N_TOK   49
#define HEADS   8
#define KDIM    1024
#define M_TOTAL (B_DIM * N_TOK)      // 25088
#define XSTRIDE (C_DIM * N_TOK)      // 50176
#define QKV_SCALE 0.08838834764831845f
#define NSTAGE  3
#define BKT     64                   // k per stage (halves)
#define NIT     (KDIM / BKT)         // 16
#define LDAH    72                   // smem leading dim in halves (64 + 8 pad)

// ---------------- scratch ----------------
__device__ __align__(16) __half g_a [(size_t)M_TOTAL * KDIM];   // x transposed [M,K] fp16
__device__ __align__(16) __half g_wc[3072 * KDIM];              // [Wq;Wkv] rows fp16
__device__ __align__(16) __half g_wp[1024 * KDIM];              // Wproj rows fp16
__device__ __align__(16) float  g_q [(size_t)M_TOTAL * C_DIM];
__device__ __align__(16) float  g_k [(size_t)M_TOTAL * C_DIM];
__device__ __align__(16) float  g_v [(size_t)M_TOTAL * C_DIM];
__device__ __align__(16) __half g_ao[(size_t)M_TOTAL * C_DIM];  // attn out [M,K] fp16

// ---------------- helpers ----------------
__device__ __forceinline__ uint32_t sptr(const void* p) {
    return (uint32_t)__cvta_generic_to_shared(p);
}
__device__ __forceinline__ void cp16(uint32_t d, const void* s) {
    asm volatile("cp.async.cg.shared.global [%0], [%1], 16;\n" :: "r"(d), "l"(s));
}
#define CP_COMMIT() asm volatile("cp.async.commit_group;\n")
#define CP_WAIT2()  asm volatile("cp.async.wait_group 2;\n")

// ---------------- smem stage layout (halves) ----------------
#define AS_HALVES  (128 * LDAH)               // 9216
#define STG_HALVES (2 * AS_HALVES)            // 18432
#define GEMM_SMEM_BYTES (NSTAGE * STG_HALVES * 2)   // 110592

// =====================================================================
// prep: transpose x (B, C, 49) -> g_a[(b*49+n), k] fp16
// =====================================================================
__global__ __launch_bounds__(256) void xprep_kernel(const float* __restrict__ x)
{
    __shared__ float tile[32][50];
    const int b  = blockIdx.y;
    const int k0 = blockIdx.x * 32;
    const float* xb = x + (size_t)b * XSTRIDE + (size_t)k0 * 49;
    for (int idx = threadIdx.x; idx < 32 * 49; idx += 256) {
        int kk = idx / 49, nn = idx - kk * 49;
        tile[kk][nn] = xb[idx];
    }
    __syncthreads();
    for (int idx = threadIdx.x; idx < 49 * 32; idx += 256) {
        int nn = idx >> 5, kk = idx & 31;
        g_a[(size_t)(b * 49 + nn) * KDIM + k0 + kk] = __float2half_rn(tile[kk][nn]);
    }
}

// =====================================================================
// prep: weights -> fp16. sel: 0=Wq->wc[0:], 1=Wkv->wc[1024K:], 2=Wproj->wp
// =====================================================================
__global__ __launch_bounds__(256) void wprep_kernel(
    const float* __restrict__ src, int sel, int nelem)
{
    int i = (blockIdx.x * 256 + threadIdx.x) * 4;
    if (i >= nelem) return;
    __half* dst;
    if (sel == 0)      dst = g_wc;
    else if (sel == 1) dst = g_wc + 1024 * KDIM;
    else               dst = g_wp;
    float4 v = *reinterpret_cast<const float4*>(src + i);
    __half2* dp = reinterpret_cast<__half2*>(dst + i);
    dp[0] = __floats2half2_rn(v.x, v.y);
    dp[1] = __floats2half2_rn(v.z, v.w);
}

// =====================================================================
// GEMM building blocks: fp16 wmma m16n16k16, CTA 128x128, warp 32x64,
// BK=64, 3-stage cp.async pipeline.
// A row-major [m][k] in smem (ld 72); B as [j][k] (ld 72), col_major frag.
// =====================================================================
using FragA = wmma::fragment<wmma::matrix_a, 16, 16, 16, half, wmma::row_major>;
using FragB = wmma::fragment<wmma::matrix_b, 16, 16, 16, half, wmma::col_major>;
using FragC = wmma::fragment<wmma::accumulator, 16, 16, 16, float>;

__device__ __forceinline__ void load_stage(
    __half* smp, const __half* __restrict__ A, const __half* __restrict__ W,
    int m0, int J0, int s, int k0, int r0, int cq)
{
    __half* As = smp + s * STG_HALVES;
    __half* Bs = As + AS_HALVES;
#pragma unroll
    for (int i = 0; i < 4; i++) {
        int row = r0 + 32 * i;
        cp16(sptr(As + row * LDAH + cq), A + (size_t)(m0 + row) * KDIM + k0 + cq);
        cp16(sptr(Bs + row * LDAH + cq), W + (size_t)(J0 + row) * KDIM + k0 + cq);
    }
}

__device__ __forceinline__ void gemm_mainloop(
    __half* smp, const __half* __restrict__ A, const __half* __restrict__ W,
    int m0, int J0, FragC acc[2][4])
{
    const int tid = threadIdx.x;
    const int wid = tid >> 5;
    const int wm  = wid & 3;          // 0..3 (M)
    const int wn  = wid >> 2;         // 0..1 (N)
    const int r0  = tid >> 3;         // 0..31
    const int cq  = (tid & 7) * 8;    // half-offset of 16B chunk

#pragma unroll
    for (int i = 0; i < 2; i++)
#pragma unroll
        for (int j = 0; j < 4; j++) wmma::fill_fragment(acc[i][j], 0.0f);

    load_stage(smp, A, W, m0, J0, 0, 0, r0, cq);
    CP_COMMIT();
    load_stage(smp, A, W, m0, J0, 1, BKT, r0, cq);
    CP_COMMIT();

    for (int it = 0; it < NIT; it++) {
        const int pf = it + NSTAGE - 1;
        if (pf < NIT)
            load_stage(smp, A, W, m0, J0, pf % NSTAGE, pf * BKT, r0, cq);
        CP_COMMIT();
        CP_WAIT2();
        __syncthreads();

        const __half* As = smp + (it % NSTAGE) * STG_HALVES;
        const __half* Bs = As + AS_HALVES;
#pragma unroll
        for (int ks = 0; ks < 4; ks++) {
            const int kk = ks * 16;
            FragA af[2];
            FragB bf[4];
#pragma unroll
            for (int i = 0; i < 2; i++)
                wmma::load_matrix_sync(af[i], As + (wm * 32 + 16 * i) * LDAH + kk, LDAH);
#pragma unroll
            for (int j = 0; j < 4; j++)
                wmma::load_matrix_sync(bf[j], Bs + (wn * 64 + 16 * j) * LDAH + kk, LDAH);
#pragma unroll
            for (int i = 0; i < 2; i++)
#pragma unroll
                for (int j = 0; j < 4; j++)
                    wmma::mma_sync(acc[i][j], af[i], bf[j], acc[i][j]);
        }
        __syncthreads();
    }
}

// stage accumulators to smem Cs (128 x 132 floats)
__device__ __forceinline__ void stage_acc(float* Cs, FragC acc[2][4])
{
    const int wid = threadIdx.x >> 5;
    const int wm  = wid & 3;
    const int wn  = wid >> 2;
#pragma unroll
    for (int i = 0; i < 2; i++)
#pragma unroll
        for (int j = 0; j < 4; j++)
            wmma::store_matrix_sync(Cs + (wm * 32 + 16 * i) * 132 + wn * 64 + 16 * j,
                                    acc[i][j], 132, wmma::mem_row_major);
}

// =====================================================================
// Kernel: QKV GEMM. grid (24, 196). Scatter epilogue with bias/scale.
// =====================================================================
__global__ __launch_bounds__(256, 2) void qkv_gemm_kernel(
    const float* __restrict__ bq, const float* __restrict__ bkv)
{
    extern __shared__ __align__(16) __half smp[];
    const int m0 = blockIdx.y * 128;
    const int J0 = blockIdx.x * 128;
    const int tid = threadIdx.x;

    FragC acc[2][4];
    gemm_mainloop(smp, g_a, g_wc, m0, J0, acc);

    float* Cs = reinterpret_cast<float*>((void*)smp);
    __syncthreads();
    stage_acc(Cs, acc);
    __syncthreads();

    const int jloc = tid & 127;          // per-thread fixed column
    const int ibase = tid >> 7;          // 0..1
    const int J = J0 + jloc;
#pragma unroll 8
    for (int p = 0; p < 64; p++) {
        int i = ibase + p * 2;
        float v = Cs[i * 132 + jloc];
        int row = m0 + i;
        int b = row / 49;
        int n = row - b * 49;
        if (J < 1024) {
            int c = J;
            g_q[(((size_t)(b * 8 + (c >> 7))) * 49 + n) * 128 + (c & 127)] =
                (v + bq[c]) * QKV_SCALE;
        } else if (J < 2048) {
            int c = J - 1024;
            g_k[(((size_t)(b * 8 + (c >> 7))) * 49 + n) * 128 + (c & 127)] = v + bkv[c];
        } else {
            int c = J - 2048;
            g_v[(((size_t)(b * 8 + (c >> 7))) * 49 + n) * 128 + (c & 127)] = v + bkv[c + 1024];
        }
    }
}

// =====================================================================
// Kernel: attention per (b,h). Output fp16 to g_ao (B,N,C).
// =====================================================================
#define ATT_SMEM_FLOATS (6272 + 6336 + 6272 + 49 * 52 + 176)
#define ATT_SMEM_BYTES  (ATT_SMEM_FLOATS * 4)

__global__ __launch_bounds__(256) void attn_kernel(
    const float* __restrict__ rpb_table, const float* __restrict__ w_mix)
{
    extern __shared__ __align__(16) float sm[];
    float* q_s   = sm;
    float* k_s   = sm + 6272;
    float* v_s   = sm + 6272 + 6336;
    float* p_s   = v_s + 6272;
    float* rpb_s = p_s + 49 * 52;

    const int bh   = blockIdx.x;
    const int h    = bh & 7;
    const int b    = bh >> 3;
    const int tid  = threadIdx.x;
    const int lane = tid & 31;
    const int wid  = tid >> 5;

    const float* qg = g_q + (size_t)bh * 6272;
    const float* kg = g_k + (size_t)bh * 6272;
    const float* vg = g_v + (size_t)bh * 6272;

    for (int i = tid; i < 6272; i += 256) {
        q_s[i] = qg[i];
        v_s[i] = vg[i];
        int m = i >> 7, d = i & 127;
        k_s[m * 129 + d] = kg[i];
    }
    if (tid < 169) rpb_s[tid] = rpb_table[tid * 8 + h];

    float wa = w_mix[0], wb = w_mix[1];
    float mw = fmaxf(wa, wb);
    float ea = __expf(wa - mw), eb = __expf(wb - mw);
    float w0 = ea / (ea + eb), w1 = eb / (ea + eb);
    __syncthreads();

    const int m_a = lane;
    const int m_b = lane + 32;
    const bool act = (m_b < 49);
    const int m_bc = act ? m_b : 48;
    const int ja0 = m_a / 7,  ja1 = m_a - ja0 * 7;
    const int jb0 = m_bc / 7, jb1 = m_bc - jb0 * 7;

    for (int n = wid; n < 49; n += 8) {
        float s0 = 0.f, s1 = 0.f;
        const float* qrow = q_s + (n << 7);
        const float* k0p  = k_s + m_a * 129;
        const float* k1p  = k_s + m_bc * 129;
#pragma unroll 8
        for (int d = 0; d < 128; d++) {
            float qd = qrow[d];
            s0 = fmaf(qd, k0p[d], s0);
            s1 = fmaf(qd, k1p[d], s1);
        }
        int i0 = n / 7, i1 = n - i0 * 7;
        s0 += rpb_s[(i0 - ja0 + 6) * 13 + (i1 - ja1 + 6)];
        s1 += rpb_s[(i0 - jb0 + 6) * 13 + (i1 - jb1 + 6)];

        float s1v = act ? s1 : -1e30f;
        float mx = fmaxf(s0, s1v);
#pragma unroll
        for (int off = 16; off > 0; off >>= 1)
            mx = fmaxf(mx, __shfl_xor_sync(0xffffffffu, mx, off));
        float e0 = __expf(s0 - mx);
        float e1 = act ? __expf(s1 - mx) : 0.f;
        float sum = e0 + e1;
#pragma unroll
        for (int off = 16; off > 0; off >>= 1)
            sum += __shfl_xor_sync(0xffffffffu, sum, off);
        float inv = __frcp_rn(sum);

        float r0 = fmaxf(s0, 0.f); r0 *= r0;
        float r1 = fmaxf(s1, 0.f); r1 *= r1;
        p_s[n * 52 + m_a] = w0 * e0 * inv + w1 * r0;
        if (act) p_s[n * 52 + m_b] = w0 * e1 * inv + w1 * r1;
    }
    __syncthreads();

    for (int n = wid; n < 49; n += 8) {
        float4 acc = make_float4(0.f, 0.f, 0.f, 0.f);
        const float* pp = p_s + n * 52;
        const float* vb = v_s + (lane << 2);
#pragma unroll 7
        for (int m = 0; m < 49; m++) {
            float p = pp[m];
            float4 vv = *reinterpret_cast<const float4*>(vb + (m << 7));
            acc.x = fmaf(p, vv.x, acc.x);
            acc.y = fmaf(p, vv.y, acc.y);
            acc.z = fmaf(p, vv.z, acc.z);
            acc.w = fmaf(p, vv.w, acc.w);
        }
        __half2* dp = reinterpret_cast<__half2*>(
            g_ao + ((size_t)(b * 49 + n)) * 1024 + h * 128 + (lane << 2));
        dp[0] = __floats2half2_rn(acc.x, acc.y);
        dp[1] = __floats2half2_rn(acc.z, acc.w);
    }
}

// =====================================================================
// Kernel: output projection GEMM. grid (8, 196). Transposed store + bias.
// =====================================================================
__global__ __launch_bounds__(256, 2) void proj_gemm_kernel(
    const float* __restrict__ bproj, float* __restrict__ out)
{
    extern __shared__ __align__(16) __half smp[];
    const int m0 = blockIdx.y * 128;
    const int J0 = blockIdx.x * 128;
    const int tid = threadIdx.x;

    FragC acc[2][4];
    gemm_mainloop(smp, g_ao, g_wp, m0, J0, acc);

    float* Cs = reinterpret_cast<float*>((void*)smp);
    __syncthreads();
    stage_acc(Cs, acc);
    __syncthreads();

    // transposed store: i (row == n) fast for coalescing on out[b, c, n]
    const int iloc = tid & 127;
    const int jbase = tid >> 7;          // 0..1
#pragma unroll 8
    for (int p = 0; p < 64; p++) {
        int j = jbase + p * 2;
        int J = J0 + j;
        float v = Cs[iloc * 132 + j] + bproj[J];
        int row = m0 + iloc;
        int bb = row / 49;
        int nn = row - bb * 49;
        out[(size_t)bb * XSTRIDE + (size_t)J * 49 + nn] = v;
    }
}

// =====================================================================
// launcher
// =====================================================================
extern "C" void kernel_launch(void* const* d_in, const int* in_sizes, int n_in,
                              void* d_out, int out_size)
{
    const float* x         = (const float*)d_in[0];
    const float* Wq        = (const float*)d_in[1];
    const float* bq        = (const float*)d_in[2];
    const float* Wkv       = (const float*)d_in[3];
    const float* bkv       = (const float*)d_in[4];
    const float* rpb_table = (const float*)d_in[5];
    const float* w_mix     = (const float*)d_in[6];
    const float* Wproj     = (const float*)d_in[7];
    const float* bproj     = (const float*)d_in[8];
    float* out = (float*)d_out;

    cudaFuncSetAttribute(qkv_gemm_kernel,
        cudaFuncAttributeMaxDynamicSharedMemorySize, GEMM_SMEM_BYTES);
    cudaFuncSetAttribute(proj_gemm_kernel,
        cudaFuncAttributeMaxDynamicSharedMemorySize, GEMM_SMEM_BYTES);
    cudaFuncSetAttribute(attn_kernel,
        cudaFuncAttributeMaxDynamicSharedMemorySize, ATT_SMEM_BYTES);

    // preps
    dim3 gx(32, 512);
    xprep_kernel<<<gx, 256>>>(x);
    wprep_kernel<<<(1024 * KDIM) / 1024, 256>>>(Wq, 0, 1024 * KDIM);
    wprep_kernel<<<(2048 * KDIM) / 1024, 256>>>(Wkv, 1, 2048 * KDIM);
    wprep_kernel<<<(1024 * KDIM) / 1024, 256>>>(Wproj, 2, 1024 * KDIM);

    dim3 g1(24, 196);
    qkv_gemm_kernel<<<g1, 256, GEMM_SMEM_BYTES>>>(bq, bkv);

    attn_kernel<<<B_DIM * HEADS, 256, ATT_SMEM_BYTES>>>(rpb_table, w_mix);

    dim3 g3(8, 196);
    proj_gemm_kernel<<<g3, 256, GEMM_SMEM_BYTES>>>(bproj, out);
}